// round 10
// baseline (speedup 1.0000x reference)
#include <cuda_runtime.h>
#include <math.h>

#define NN 100000
#define NE 1600000
#define C  128
#define OC 64
#define NG 64

// ---------------- static device scratch (zero-initialized .bss) --------------
__device__ float g_bufA[(size_t)NN * C];   // z (agg out) / h2 (gemm2 in-place)
__device__ float g_bufB[(size_t)NN * C];   // saved copy of x during the launch
__device__ int   g_col[NE];
__device__ int   g_cnt[NN];                // zeroed inline by k_scan each replay
__device__ int   g_rowptr[NN + 1];
__device__ int   g_fillptr[NN];
__device__ float g_dinv[NN];
__device__ int   g_gcnt[NG];               // zeroed inline by k_scan each replay
__device__ int   g_goff[NG + 1];

__device__ __forceinline__ int detect64(const int* e32) {
    int is64 = 1;
    #pragma unroll
    for (int i = 0; i < 8; i++) if (e32[2 * i + 1] != 0) is64 = 0;
    return is64;
}

// idx 0: in-degree histogram + per-graph node histogram
__global__ void k_hist_all(const void* ei, const void* bat, int E, int N) {
    int tid = blockIdx.x * blockDim.x + threadIdx.x;
    int stride = gridDim.x * blockDim.x;
    int is64 = detect64((const int*)ei);
    if (is64) {
        const long long* e = (const long long*)ei;
        for (int i = tid; i < E; i += stride)
            atomicAdd(&g_cnt[(int)e[(size_t)E + i]], 1);
        const long long* b = (const long long*)bat;
        for (int i = tid; i < N; i += stride) atomicAdd(&g_gcnt[(int)b[i]], 1);
    } else {
        const int* e = (const int*)ei;
        for (int i = tid; i < E; i += stride)
            atomicAdd(&g_cnt[e[E + i]], 1);
        const int* b = (const int*)bat;
        for (int i = tid; i < N; i += stride) atomicAdd(&g_gcnt[b[i]], 1);
    }
}

// idx 1: single-block fused scan: rowptr/fillptr, dinv, zero cnt, rowptr[N]=E,
// goff from gcnt, zero gcnt.
__global__ void k_scan(int n) {
    __shared__ int wsum[32];
    __shared__ int carry_s;
    int tid = threadIdx.x;
    int lane = tid & 31, wid = tid >> 5;
    if (tid == 0) carry_s = 0;
    __syncthreads();

    for (int base = 0; base < n; base += 1024) {
        int i = base + tid;
        int v = (i < n) ? g_cnt[i] : 0;
        int x = v;
        #pragma unroll
        for (int o = 1; o < 32; o <<= 1) {
            int t = __shfl_up_sync(~0u, x, o);
            if (lane >= o) x += t;
        }
        if (lane == 31) wsum[wid] = x;
        __syncthreads();
        if (wid == 0) {
            int s = wsum[lane];
            #pragma unroll
            for (int o = 1; o < 32; o <<= 1) {
                int t = __shfl_up_sync(~0u, s, o);
                if (lane >= o) s += t;
            }
            wsum[lane] = s;
        }
        __syncthreads();
        int carry = carry_s;
        int warpoff = (wid > 0) ? wsum[wid - 1] : 0;
        int excl = carry + warpoff + x - v;
        if (i < n) {
            g_rowptr[i] = excl;
            g_fillptr[i] = excl;
            g_dinv[i] = rsqrtf((float)(v + 1));
            g_cnt[i] = 0;
        }
        __syncthreads();
        if (tid == 1023) carry_s = carry + wsum[31];
        __syncthreads();
    }
    if (tid == 0) {
        g_rowptr[n] = carry_s;
        int s = 0;
        #pragma unroll
        for (int g = 0; g < NG; g++) {
            g_goff[g] = s;
            s += g_gcnt[g];
            g_gcnt[g] = 0;
        }
        g_goff[NG] = s;
    }
}

// idx 2: CSR column fill (measured 27us)
__global__ void k_fill(const void* ei, int E) {
    int tid = blockIdx.x * blockDim.x + threadIdx.x;
    int stride = gridDim.x * blockDim.x;
    int is64 = detect64((const int*)ei);
    if (is64) {
        const long long* e = (const long long*)ei;
        for (int i = tid; i < E; i += stride) {
            int d = (int)e[(size_t)E + i];
            int s = (int)e[i];
            g_col[atomicAdd(&g_fillptr[d], 1)] = s;
        }
    } else {
        const int* e = (const int*)ei;
        for (int i = tid; i < E; i += stride) {
            int d = e[E + i];
            int s = e[i];
            g_col[atomicAdd(&g_fillptr[d], 1)] = s;
        }
    }
}

// idx 3 (PROFILED) / idx 5: z_i = di*(di*u_i + sum_j dj*u_j)
// 4 nodes per warp (8-lane sub-warps, 32 channels each), 4 channel groups
// across the grid => 4 independent edge-chains per warp, MLP ~32/warp.
// Gather per sub-warp = 8 lanes x float4 = 128B line, fully coalesced.
__global__ __launch_bounds__(256) void k_agg(
    const float* __restrict__ Uin, float* __restrict__ Zout,
    float* __restrict__ save, int n)
{
    int gwarp = (blockIdx.x * blockDim.x + threadIdx.x) >> 5;
    int lane = threadIdx.x & 31;
    int sub = lane >> 3;       // node slot within warp (0..3)
    int sl  = lane & 7;        // lane within sub-warp (0..7)

    int wpg = (n + 3) >> 2;            // warps per channel group
    int cg = gwarp / wpg;              // channel group (0..3)
    int node = (gwarp - cg * wpg) * 4 + sub;
    if (node >= n || cg >= 4) return;

    int poff = cg * 8;                 // float4 offset of this 32-ch group

    const float4* U4 = (const float4*)Uin;
    size_t base = (size_t)node * 32 + poff + sl;

    float di = g_dinv[node];
    float4 s4 = U4[base];
    if (save) ((float4*)save)[base] = s4;
    float4 acc = make_float4(s4.x * di, s4.y * di, s4.z * di, s4.w * di);

    int e = g_rowptr[node];
    int end = g_rowptr[node + 1];

    for (; e + 8 <= end; e += 8) {
        int s[8];
        #pragma unroll
        for (int j = 0; j < 8; j++) s[j] = g_col[e + j];
        float w[8];
        #pragma unroll
        for (int j = 0; j < 8; j++) w[j] = g_dinv[s[j]];
        float4 v[8];
        #pragma unroll
        for (int j = 0; j < 8; j++) v[j] = U4[(size_t)s[j] * 32 + poff + sl];
        #pragma unroll
        for (int j = 0; j < 8; j++) {
            acc.x = fmaf(w[j], v[j].x, acc.x);
            acc.y = fmaf(w[j], v[j].y, acc.y);
            acc.z = fmaf(w[j], v[j].z, acc.z);
            acc.w = fmaf(w[j], v[j].w, acc.w);
        }
    }
    for (; e < end; e++) {
        int s = g_col[e];
        float w = g_dinv[s];
        float4 v = U4[(size_t)s * 32 + poff + sl];
        acc.x = fmaf(w, v.x, acc.x);
        acc.y = fmaf(w, v.y, acc.y);
        acc.z = fmaf(w, v.z, acc.z);
        acc.w = fmaf(w, v.w, acc.w);
    }

    ((float4*)Zout)[base] =
        make_float4(di * acc.x, di * acc.y, di * acc.z, di * acc.w);
}

// GEMM body: H = relu(Z @ W + b). 64-row tile, full W in smem, k-paired.
// In-place safe (blocks only read their own 64 rows before storing).
__device__ __forceinline__ void gemm_body(
    const float* __restrict__ Z, const float* __restrict__ W,
    const float* __restrict__ bias, float* __restrict__ H, int n, int blk)
{
    __shared__ float Ws[C * C];      // 64 KB
    __shared__ float Zs[64 * C];     // 32 KB
    int tid = threadIdx.x;
    int row0 = blk * 64;

    for (int i = tid; i < C * C; i += 256) Ws[i] = W[i];
    for (int i = tid; i < 64 * C; i += 256) {
        int r = row0 + (i >> 7);
        Zs[i] = (r < n) ? Z[(size_t)r * C + (i & 127)] : 0.0f;
    }
    __syncthreads();

    int tn = tid & 31;    // cols [tn*4, tn*4+4)
    int tm = tid >> 5;    // rows [tm*8, tm*8+8)
    float acc[8][4];
    #pragma unroll
    for (int r = 0; r < 8; r++)
        #pragma unroll
        for (int c = 0; c < 4; c++) acc[r][c] = 0.0f;

    #pragma unroll 8
    for (int k2 = 0; k2 < C / 2; k2++) {
        float4 wv0 = *(const float4*)&Ws[(2 * k2) * C + tn * 4];
        float4 wv1 = *(const float4*)&Ws[(2 * k2 + 1) * C + tn * 4];
        #pragma unroll
        for (int r = 0; r < 8; r++) {
            float2 z = *(const float2*)&Zs[(tm * 8 + r) * C + 2 * k2];
            acc[r][0] += z.x * wv0.x + z.y * wv1.x;
            acc[r][1] += z.x * wv0.y + z.y * wv1.y;
            acc[r][2] += z.x * wv0.z + z.y * wv1.z;
            acc[r][3] += z.x * wv0.w + z.y * wv1.w;
        }
    }

    float4 bv = ((const float4*)bias)[tn];
    #pragma unroll
    for (int r = 0; r < 8; r++) {
        int row = row0 + tm * 8 + r;
        if (row < n) {
            float4 o;
            o.x = fmaxf(acc[r][0] + bv.x, 0.f);
            o.y = fmaxf(acc[r][1] + bv.y, 0.f);
            o.z = fmaxf(acc[r][2] + bv.z, 0.f);
            o.w = fmaxf(acc[r][3] + bv.w, 0.f);
            *(float4*)&H[(size_t)row * C + tn * 4] = o;
        }
    }
}

// idx 4: gemm1
__global__ __launch_bounds__(256, 2) void k_gemm(
    const float* __restrict__ Z, const float* __restrict__ W,
    const float* __restrict__ bias, float* __restrict__ H, int n)
{
    gemm_body(Z, W, bias, H, n, blockIdx.x);
}

// idx 6: gemm2 fused with restore (blocks >= gb copy bufB -> xbuf)
__global__ __launch_bounds__(256, 2) void k_gemm_rest(
    const float* __restrict__ Z, const float* __restrict__ W,
    const float* __restrict__ bias, float* __restrict__ H, int n, int gb,
    float* __restrict__ xdst, const float* __restrict__ xsrc, int n4, int rb)
{
    if (blockIdx.x >= gb) {
        int tid = (blockIdx.x - gb) * 256 + threadIdx.x;
        int stride = rb * 256;
        const float4* s4 = (const float4*)xsrc;
        float4* d4 = (float4*)xdst;
        for (int i = tid; i < n4; i += stride) d4[i] = s4[i];
        return;
    }
    gemm_body(Z, W, bias, H, n, blockIdx.x);
}

// idx 7: fused mean-pool + linear head, one block per graph
__global__ __launch_bounds__(256) void k_poolhead(
    const float* __restrict__ H, const float* __restrict__ Wl,
    const float* __restrict__ bl, float* __restrict__ out)
{
    __shared__ float4 sh[8][32];
    __shared__ float pooled[C];
    int g = blockIdx.x;
    int rr = threadIdx.x >> 5;
    int c4 = threadIdx.x & 31;
    int s = g_goff[g], e = g_goff[g + 1];
    const float4* H4 = (const float4*)H;
    float4 acc = make_float4(0.f, 0.f, 0.f, 0.f);
    for (int r = s + rr; r < e; r += 8) {
        float4 v = H4[(size_t)r * 32 + c4];
        acc.x += v.x; acc.y += v.y; acc.z += v.z; acc.w += v.w;
    }
    sh[rr][c4] = acc;
    __syncthreads();
    if (rr == 0) {
        #pragma unroll
        for (int j = 1; j < 8; j++) {
            float4 v = sh[j][c4];
            acc.x += v.x; acc.y += v.y; acc.z += v.z; acc.w += v.w;
        }
        float inv = 1.0f / fmaxf((float)(e - s), 1.0f);
        pooled[c4 * 4 + 0] = acc.x * inv;
        pooled[c4 * 4 + 1] = acc.y * inv;
        pooled[c4 * 4 + 2] = acc.z * inv;
        pooled[c4 * 4 + 3] = acc.w * inv;
    }
    __syncthreads();
    if (threadIdx.x < OC) {
        int o = threadIdx.x;
        float a = bl[o];
        #pragma unroll 4
        for (int k = 0; k < C; k++) a += pooled[k] * Wl[k * OC + o];
        out[g * OC + o] = a;
    }
}

// ---------------- launch (8 nodes) -------------------------------------------
extern "C" void kernel_launch(void* const* d_in, const int* in_sizes, int n_in,
                              void* d_out, int out_size) {
    float*       xbuf = (float*)d_in[0];          // harness buffer; restored each call
    const void*  ei   = d_in[1];
    const void*  bat  = d_in[2];
    const float* W1   = (const float*)d_in[3];
    const float* b1   = (const float*)d_in[4];
    const float* W2   = (const float*)d_in[5];
    const float* b2   = (const float*)d_in[6];
    const float* Wl   = (const float*)d_in[7];
    const float* bl   = (const float*)d_in[8];
    float* out = (float*)d_out;

    int N = in_sizes[0] / C;
    int E = in_sizes[1] / 2;
    int gb = (N + 63) / 64;
    int wpg = (N + 3) / 4;                    // warps per channel group
    int ab = (wpg * 4 * 32 + 255) / 256;      // agg blocks (4 ch groups)
    int rb = 512;                             // restore blocks appended to gemm2

    k_hist_all <<<1024, 256>>>(ei, bat, E, N);                       // 0
    k_scan     <<<1, 1024>>>(N);                                     // 1
    k_fill     <<<1024, 256>>>(ei, E);                               // 2
    // layer 1: aggregate x (harness-buffer gather), save x -> bufB
    k_agg      <<<ab, 256>>>(xbuf, g_bufA, g_bufB, N);               // 3  <-- profiled
    // gemm1 writes h1 INTO the harness x buffer (fast-gather pages)
    k_gemm     <<<gb, 256>>>(g_bufA, W1, b1, xbuf, N);               // 4
    // layer 2: aggregate h1 from the harness buffer
    k_agg      <<<ab, 256>>>(xbuf, g_bufA, nullptr, N);              // 5
    // gemm2 in-place on bufA + restore x from bufB (fused)
    k_gemm_rest<<<gb + rb, 256>>>(g_bufA, W2, b2, g_bufA, N, gb,
                                  xbuf, g_bufB, N * 32, rb);         // 6
    k_poolhead <<<NG, 256>>>(g_bufA, Wl, bl, out);                   // 7
}